// round 1
// baseline (speedup 1.0000x reference)
#include <cuda_runtime.h>
#include <math.h>

// Problem shape (fixed by dataset): x[4,4096,64], y[4,4096,64], mu[64,1], logs2diag[64]
// out[4,4096,4096] fp32.
#define BB 4
#define NN 4096
#define MM 4096
#define DD 64

// Scratch (device globals; no allocation allowed in kernel_launch).
__device__ float  g_Xs[BB * NN * DD];   // scaled x rows (x * exp(0.5*logs2))
__device__ float  g_Ys[BB * MM * DD];   // scaled y rows
__device__ float4 g_xr[BB * NN];        // per-row {cos(mx), sin(mx), 0.5*||x_||^2, 0}
__device__ float4 g_yr[BB * MM];        // per-row {cos(my), sin(my), 0.5*||y_||^2, 0}

// ---------------------------------------------------------------------------
// Pass 1: per-row precompute.
//   mx  = sum_d x[d]*mu[d]           (unscaled x, matching reference)
//   x_  = x * exp(0.5*logs2)         (stored for the GEMM)
//   h2  = 0.5 * sum_d x_[d]^2
//   cos/sin of mx computed in double (exact trig identity later:
//   cos(mx-my) = cos mx * cos my + sin mx * sin my)
// ---------------------------------------------------------------------------
__global__ void precomp_kernel(const float* __restrict__ src,
                               const float* __restrict__ mu,
                               const float* __restrict__ logs2,
                               int nrows, int isY)
{
    int r = blockIdx.x * blockDim.x + threadIdx.x;
    if (r >= nrows) return;

    float*  dst = isY ? g_Ys : g_Xs;
    float4* ri  = isY ? g_yr : g_xr;

    const float4* p = (const float4*)(src + (size_t)r * DD);
    float4*       q = (float4*)(dst + (size_t)r * DD);
    const float4* muv4 = (const float4*)mu;
    const float4* l4   = (const float4*)logs2;

    float m = 0.f, ss = 0.f;
#pragma unroll
    for (int d4 = 0; d4 < DD / 4; d4++) {
        float4 v  = p[d4];
        float4 l  = l4[d4];
        float4 mv = muv4[d4];
        float s0 = expf(0.5f * l.x), s1 = expf(0.5f * l.y);
        float s2 = expf(0.5f * l.z), s3 = expf(0.5f * l.w);
        float4 vs = make_float4(v.x * s0, v.y * s1, v.z * s2, v.w * s3);
        q[d4] = vs;
        ss += vs.x * vs.x + vs.y * vs.y + vs.z * vs.z + vs.w * vs.w;
        m = fmaf(v.x, mv.x, m);
        m = fmaf(v.y, mv.y, m);
        m = fmaf(v.z, mv.z, m);
        m = fmaf(v.w, mv.w, m);
    }
    double sd, cd;
    sincos((double)m, &sd, &cd);
    ri[r] = make_float4((float)cd, (float)sd, 0.5f * ss, 0.f);
}

// ---------------------------------------------------------------------------
// Pass 2: tiled pairwise kernel.
//   128x128 output tile per CTA, 256 threads, 8x8 microtile per thread.
//   K=64 processed in two 32-wide chunks through k-major SMEM tiles (32KB).
//   Epilogue fuses:  out = (cx*cy + sx*sy) * exp2(log2e * min(xy - h2x - h2y, 0))
// ---------------------------------------------------------------------------
__global__ void __launch_bounds__(256, 2)
pairwise_kernel(float* __restrict__ out)
{
    __shared__ float Xt[32][128];   // [k][n_local]
    __shared__ float Yt[32][128];   // [k][m_local]

    const int b  = blockIdx.z;
    const int n0 = blockIdx.y * 128;
    const int m0 = blockIdx.x * 128;
    const int tid = threadIdx.x;
    const int ti = tid >> 4;        // 0..15 -> n microtile
    const int tj = tid & 15;        // 0..15 -> m microtile

    const float* Xg = g_Xs + ((size_t)b * NN + n0) * DD;
    const float* Yg = g_Ys + ((size_t)b * MM + m0) * DD;

    float acc[8][8];
#pragma unroll
    for (int i = 0; i < 8; i++)
#pragma unroll
        for (int j = 0; j < 8; j++) acc[i][j] = 0.f;

#pragma unroll
    for (int kc = 0; kc < 2; kc++) {
        // Load 128 rows x 32 k of each operand, transposing into k-major SMEM.
        // 1024 float4 per operand, 4 per thread; 8 consecutive threads read a
        // contiguous 128B row segment (coalesced).
#pragma unroll
        for (int it = 0; it < 4; it++) {
            int f   = tid + 256 * it;     // float4 index 0..1023
            int row = f >> 3;             // 0..127
            int c4  = (f & 7) << 2;       // k offset within chunk: 0,4,...,28
            float4 v = *(const float4*)(Xg + row * DD + kc * 32 + c4);
            Xt[c4 + 0][row] = v.x; Xt[c4 + 1][row] = v.y;
            Xt[c4 + 2][row] = v.z; Xt[c4 + 3][row] = v.w;
            float4 w = *(const float4*)(Yg + row * DD + kc * 32 + c4);
            Yt[c4 + 0][row] = w.x; Yt[c4 + 1][row] = w.y;
            Yt[c4 + 2][row] = w.z; Yt[c4 + 3][row] = w.w;
        }
        __syncthreads();

#pragma unroll
        for (int k = 0; k < 32; k++) {
            float4 a0 = *(const float4*)&Xt[k][ti * 8];
            float4 a1 = *(const float4*)&Xt[k][ti * 8 + 4];
            float4 b0 = *(const float4*)&Yt[k][tj * 8];
            float4 b1 = *(const float4*)&Yt[k][tj * 8 + 4];
            float av[8] = {a0.x, a0.y, a0.z, a0.w, a1.x, a1.y, a1.z, a1.w};
            float bv[8] = {b0.x, b0.y, b0.z, b0.w, b1.x, b1.y, b1.z, b1.w};
#pragma unroll
            for (int i = 0; i < 8; i++)
#pragma unroll
                for (int j = 0; j < 8; j++)
                    acc[i][j] = fmaf(av[i], bv[j], acc[i][j]);
        }
        __syncthreads();
    }

    // Epilogue: fused cos/exp + store.
    float4 yj[8];
#pragma unroll
    for (int j = 0; j < 8; j++)
        yj[j] = g_yr[(size_t)b * MM + m0 + tj * 8 + j];

    const float LOG2E = 1.44269504f;
#pragma unroll
    for (int i = 0; i < 8; i++) {
        float4 xi = g_xr[(size_t)b * NN + n0 + ti * 8 + i];
        float res[8];
#pragma unroll
        for (int j = 0; j < 8; j++) {
            // arg = xy - 0.5*x2 - 0.5*y2 ; clamp sqd>=0  <=>  arg<=0
            float arg = acc[i][j] - xi.z - yj[j].z;
            arg = fminf(arg, 0.0f);
            float e;
            asm("ex2.approx.f32 %0, %1;" : "=f"(e) : "f"(arg * LOG2E));
            float c = fmaf(xi.x, yj[j].x, xi.y * yj[j].y);
            res[j] = c * e;
        }
        float* orow = out + (((size_t)b * NN + n0 + ti * 8 + i) * MM + m0 + tj * 8);
        *(float4*)orow       = make_float4(res[0], res[1], res[2], res[3]);
        *(float4*)(orow + 4) = make_float4(res[4], res[5], res[6], res[7]);
    }
}

// ---------------------------------------------------------------------------
extern "C" void kernel_launch(void* const* d_in, const int* in_sizes, int n_in,
                              void* d_out, int out_size)
{
    const float* x     = (const float*)d_in[0];
    const float* y     = (const float*)d_in[1];
    const float* mu    = (const float*)d_in[2];
    const float* logs2 = (const float*)d_in[3];
    (void)in_sizes; (void)n_in; (void)out_size;

    precomp_kernel<<<(BB * NN + 127) / 128, 128>>>(x, mu, logs2, BB * NN, 0);
    precomp_kernel<<<(BB * MM + 127) / 128, 128>>>(y, mu, logs2, BB * MM, 1);

    dim3 grid(MM / 128, NN / 128, BB);
    pairwise_kernel<<<grid, 256>>>((float*)d_out);
}

// round 6
// speedup vs baseline: 2.1869x; 2.1869x over previous
#include <cuda_runtime.h>
#include <cuda_bf16.h>
#include <math.h>
#include <stdint.h>

// Shape fixed by dataset: x[4,4096,64], y[4,4096,64], mu[64,1], logs2diag[64]
#define BB 4
#define NN 4096
#define MM 4096
#define DD 64
#define KE 192                      // expanded K: [hi|lo|hi] / [hi|hi|lo]

// ---------------- device scratch (no allocation allowed) -------------------
__device__ uint4  g_Xe4[BB * NN * (KE / 8)];   // bf16 expanded X rows, 24 uint4/row
__device__ uint4  g_Ye4[BB * MM * (KE / 8)];   // bf16 expanded Y rows
__device__ float4 g_xr[BB * NN];               // {cos(mx), sin(mx), 0.5*||x_||^2, 0}
__device__ float4 g_yr[BB * MM];

__device__ __forceinline__ uint32_t smem_u32(const void* p) {
    uint32_t a;
    asm("{ .reg .u64 t; cvta.to.shared.u64 t, %1; cvt.u32.u64 %0, t; }" : "=r"(a) : "l"(p));
    return a;
}

#define SWZ(o) ((o) ^ (((o) >> 3) & 0x70))

#define LDSM_X4(r0, r1, r2, r3, addr)                                        \
    asm volatile("ldmatrix.sync.aligned.m8n8.x4.shared.b16 {%0,%1,%2,%3}, [%4];" \
                 : "=r"(r0), "=r"(r1), "=r"(r2), "=r"(r3) : "r"(addr))

#define MMA16816(d, a0, a1, a2, a3, b0, b1)                                  \
    asm volatile("mma.sync.aligned.m16n8k16.row.col.f32.bf16.bf16.f32 "      \
        "{%0,%1,%2,%3}, {%4,%5,%6,%7}, {%8,%9}, {%0,%1,%2,%3};"              \
        : "+f"((d)[0]), "+f"((d)[1]), "+f"((d)[2]), "+f"((d)[3])             \
        : "r"(a0), "r"(a1), "r"(a2), "r"(a3), "r"(b0), "r"(b1))

// ---------------- SMEM layout ----------------------------------------------
static constexpr int OFF_A  = 0;        // 3 segs x 16KB (128 rows x 128B, SW128)
static constexpr int OFF_B  = 49152;    // 3 segs x 16KB
static constexpr int OFF_XI = 98304;    // float4[128]
static constexpr int OFF_YI = 100352;   // float4[128]
static constexpr int SMEM_TOTAL = 102400;

// ---------------------------------------------------------------------------
// Pass 1: per-row precompute + bf16 split-expansion. One warp per row.
//   mx = x·mu (unscaled), row scaled by exp(0.5*logs2), h2 = 0.5*||x_||^2
//   bf16 split: x_ = hi + lo;  X: [hi|lo|hi], Y: [hi|hi|lo]
//   => X'·Y'^T = hi·hi + lo·hi + hi·lo  (missing lo·lo ~3e-5 abs)
// ---------------------------------------------------------------------------
__global__ void precomp_kernel(const float* __restrict__ src,
                               const float* __restrict__ mu,
                               const float* __restrict__ logs2, int isY)
{
    int gw = (blockIdx.x * blockDim.x + threadIdx.x) >> 5;  // global warp == row
    int l  = threadIdx.x & 31;

    float2 v   = ((const float2*)src)[gw * 32 + l];     // dims 2l, 2l+1
    float2 muv = ((const float2*)mu)[l];
    float2 ls  = ((const float2*)logs2)[l];

    float s0 = expf(0.5f * ls.x), s1 = expf(0.5f * ls.y);
    float a = v.x * s0, c = v.y * s1;
    float m  = fmaf(v.x, muv.x, v.y * muv.y);
    float ss = fmaf(a, a, c * c);
#pragma unroll
    for (int o = 16; o > 0; o >>= 1) {
        m  += __shfl_xor_sync(0xffffffffu, m, o);
        ss += __shfl_xor_sync(0xffffffffu, ss, o);
    }

    __nv_bfloat16 h0 = __float2bfloat16(a);
    __nv_bfloat16 h1 = __float2bfloat16(c);
    __nv_bfloat16 l0 = __float2bfloat16(a - __bfloat162float(h0));
    __nv_bfloat16 l1 = __float2bfloat16(c - __bfloat162float(h1));
    uint32_t hi = ((uint32_t)__bfloat16_as_ushort(h1) << 16) | __bfloat16_as_ushort(h0);
    uint32_t lo = ((uint32_t)__bfloat16_as_ushort(l1) << 16) | __bfloat16_as_ushort(l0);

    uint32_t* dst = (uint32_t*)(isY ? g_Ye4 : g_Xe4) + (size_t)gw * (KE / 2);
    if (isY) {                 // [hi | hi | lo]
        dst[l] = hi; dst[32 + l] = hi; dst[64 + l] = lo;
    } else {                   // [hi | lo | hi]
        dst[l] = hi; dst[32 + l] = lo; dst[64 + l] = hi;
    }
    if (l == 0) {
        float sn, cs;
        sincosf(m, &sn, &cs);
        float4* ri = isY ? g_yr : g_xr;
        ri[gw] = make_float4(cs, sn, 0.5f * ss, 0.f);
    }
}

// ---------------------------------------------------------------------------
// Pass 2: mma.sync bf16 GEMM tile + fused epilogue.
//   CTA: 128x128 tile, 8 warps (2x4), warp tile 64x32 = 4x4 m16n8k16 tiles.
// ---------------------------------------------------------------------------
__global__ void __launch_bounds__(256, 2)
pairwise_kernel(float* __restrict__ out)
{
    extern __shared__ char smem[];
    const uint32_t base = smem_u32(smem);
    const int tid = threadIdx.x;
    const int wid = tid >> 5;
    const int l   = tid & 31;
    const int wy  = wid >> 2;           // 0..1 : row block (64 rows)
    const int wx  = wid & 3;            // 0..3 : col block (32 cols)

    const int b  = blockIdx.z;
    const int n0 = blockIdx.y * 128;
    const int m0 = blockIdx.x * 128;

    // ---- load A and B tiles (128 rows x 192 bf16) into SW128 smem ----
    const uint4* Ag = g_Xe4 + ((size_t)b * NN + n0) * (KE / 8);
    const uint4* Bg = g_Ye4 + ((size_t)b * MM + m0) * (KE / 8);
#pragma unroll
    for (int i = 0; i < 12; i++) {
        int f   = i * 256 + tid;        // uint4 index 0..3071 (24 per row)
        int row = f / 24;
        int q   = f - row * 24;
        int seg = q >> 3;               // 0..2
        int c16 = q & 7;                // 16B chunk within 128B row
        uint32_t off = SWZ((uint32_t)(row * 128 + c16 * 16));
        *(uint4*)(smem + OFF_A + seg * 16384 + off) = Ag[f];
        *(uint4*)(smem + OFF_B + seg * 16384 + off) = Bg[f];
    }
    // row-info staging
    if (tid < 128)
        *(float4*)(smem + OFF_XI + tid * 16) = g_xr[(size_t)b * NN + n0 + tid];
    else
        *(float4*)(smem + OFF_YI + (tid - 128) * 16) = g_yr[(size_t)b * MM + m0 + (tid - 128)];
    __syncthreads();

    // ---- per-lane ldmatrix address components ----
    // A (x4 per m16 tile): lanes 0-15 -> rows 0-15 khalf 0; lanes 16-31 -> khalf 16
    const int arow  = wy * 64 + (l & 15);
    const uint32_t axor  = (uint32_t)((l & 7) * 16);
    const uint32_t ahalf = (uint32_t)((l >> 4) * 16);
    // B (x4 covers two n8 tiles): group g=l>>3: rows +(g&2)*4, khalf (g&1)*16
    const int g     = l >> 3;
    const int brow  = wx * 32 + (g & 2) * 4 + (l & 7);
    const uint32_t bxor  = (uint32_t)((l & 7) * 16);
    const uint32_t bhalf = (uint32_t)((g & 1) * 16);

    float acc[4][4][4];
#pragma unroll
    for (int mt = 0; mt < 4; mt++)
#pragma unroll
        for (int nt = 0; nt < 4; nt++)
#pragma unroll
            for (int e = 0; e < 4; e++) acc[mt][nt][e] = 0.f;

    // ---- mainloop: 12 K16 steps over 3 segments ----
#pragma unroll
    for (int ks = 0; ks < 12; ks++) {
        const int seg = ks >> 2;
        const uint32_t kb = (uint32_t)((ks & 3) * 32);
        const uint32_t baseA = base + OFF_A + seg * 16384;
        const uint32_t baseB = base + OFF_B + seg * 16384;

        uint32_t af[4][4];
#pragma unroll
        for (int mt = 0; mt < 4; mt++) {
            uint32_t addr = baseA + (uint32_t)((arow + mt * 16) * 128) + ((kb + ahalf) ^ axor);
            LDSM_X4(af[mt][0], af[mt][1], af[mt][2], af[mt][3], addr);
        }
        uint32_t bf[4][2];
#pragma unroll
        for (int p = 0; p < 2; p++) {
            uint32_t addr = baseB + (uint32_t)((brow + p * 16) * 128) + ((kb + bhalf) ^ bxor);
            uint32_t r0, r1, r2, r3;
            LDSM_X4(r0, r1, r2, r3, addr);
            bf[p * 2 + 0][0] = r0; bf[p * 2 + 0][1] = r1;
            bf[p * 2 + 1][0] = r2; bf[p * 2 + 1][1] = r3;
        }
#pragma unroll
        for (int mt = 0; mt < 4; mt++)
#pragma unroll
            for (int nt = 0; nt < 4; nt++)
                MMA16816(acc[mt][nt], af[mt][0], af[mt][1], af[mt][2], af[mt][3],
                         bf[nt][0], bf[nt][1]);
    }

    // ---- epilogue straight from registers ----
    // acc tile (mt,nt): lane l -> rows (l/4, l/4+8), cols (2*(l%4), +1)
    const float LOG2E = 1.44269504f;
    const int lr = l >> 2;          // 0..7
    const int lc = (l & 3) * 2;     // 0,2,4,6
#pragma unroll
    for (int mt = 0; mt < 4; mt++) {
        const int r0 = wy * 64 + mt * 16 + lr;
        const float4 xi0 = *(const float4*)(smem + OFF_XI + r0 * 16);
        const float4 xi1 = *(const float4*)(smem + OFF_XI + (r0 + 8) * 16);
        float* orow0 = out + ((size_t)b * NN + n0 + r0) * MM + m0;
        float* orow1 = orow0 + (size_t)8 * MM;
#pragma unroll
        for (int nt = 0; nt < 4; nt++) {
            const int c = wx * 32 + nt * 8 + lc;
            const float4 y0 = *(const float4*)(smem + OFF_YI + c * 16);
            const float4 y1 = *(const float4*)(smem + OFF_YI + (c + 1) * 16);

            float e00, e01, e10, e11;
            asm("ex2.approx.f32 %0, %1;" : "=f"(e00)
                : "f"(fminf(acc[mt][nt][0] - xi0.z - y0.z, 0.f) * LOG2E));
            asm("ex2.approx.f32 %0, %1;" : "=f"(e01)
                : "f"(fminf(acc[mt][nt][1] - xi0.z - y1.z, 0.f) * LOG2E));
            asm("ex2.approx.f32 %0, %1;" : "=f"(e10)
                : "f"(fminf(acc[mt][nt][2] - xi1.z - y0.z, 0.f) * LOG2E));
            asm("ex2.approx.f32 %0, %1;" : "=f"(e11)
                : "f"(fminf(acc[mt][nt][3] - xi1.z - y1.z, 0.f) * LOG2E));

            float c00 = fmaf(xi0.x, y0.x, xi0.y * y0.y);
            float c01 = fmaf(xi0.x, y1.x, xi0.y * y1.y);
            float c10 = fmaf(xi1.x, y0.x, xi1.y * y0.y);
            float c11 = fmaf(xi1.x, y1.x, xi1.y * y1.y);

            *(float2*)(orow0 + c) = make_float2(c00 * e00, c01 * e01);
            *(float2*)(orow1 + c) = make_float2(c10 * e10, c11 * e11);
        }
    }
}

// ---------------------------------------------------------------------------
extern "C" void kernel_launch(void* const* d_in, const int* in_sizes, int n_in,
                              void* d_out, int out_size)
{
    const float* x     = (const float*)d_in[0];
    const float* y     = (const float*)d_in[1];
    const float* mu    = (const float*)d_in[2];
    const float* logs2 = (const float*)d_in[3];
    (void)in_sizes; (void)n_in; (void)out_size;

    cudaFuncSetAttribute(pairwise_kernel,
                         cudaFuncAttributeMaxDynamicSharedMemorySize, SMEM_TOTAL);

    // one warp per row
    precomp_kernel<<<(BB * NN) / 8, 256>>>(x, mu, logs2, 0);
    precomp_kernel<<<(BB * MM) / 8, 256>>>(y, mu, logs2, 1);

    dim3 grid(MM / 128, NN / 128, BB);
    pairwise_kernel<<<grid, 256, SMEM_TOTAL>>>((float*)d_out);
}

// round 8
// speedup vs baseline: 2.2974x; 1.0505x over previous
#include <cuda_runtime.h>
#include <cuda_bf16.h>
#include <math.h>
#include <stdint.h>

// Shape fixed by dataset: x[4,4096,64], y[4,4096,64], mu[64,1], logs2diag[64]
// NOTE: resubmission of the R7 design — R7 returned "GB300 container failed
// twice" (broker infra failure; same message as the R0 stub round). Audit
// found no container-killing construct; getting one clean measurement.
#define BB 4
#define NN 4096
#define MM 4096
#define DD 64
#define KE 192                      // expanded K: [hi|lo|hi] / [hi|hi|lo]

// ---------------- device scratch (no allocation allowed) -------------------
__device__ uint4  g_Xe4[BB * NN * (KE / 8)];   // bf16 expanded X rows, 24 uint4/row
__device__ uint4  g_Ye4[BB * MM * (KE / 8)];   // bf16 expanded Y rows
__device__ float4 g_xr[BB * NN];               // {cos(mx), sin(mx), 0.5*||x_||^2, 0}
__device__ float4 g_yr[BB * MM];

__device__ __forceinline__ uint32_t smem_u32(const void* p) {
    uint32_t a;
    asm("{ .reg .u64 t; cvta.to.shared.u64 t, %1; cvt.u32.u64 %0, t; }" : "=r"(a) : "l"(p));
    return a;
}

#define SWZ(o) ((o) ^ (((o) >> 3) & 0x70))

#define CP_ASYNC16(dst, src) \
    asm volatile("cp.async.cg.shared.global [%0], [%1], 16;" \
                 :: "r"(dst), "l"(src) : "memory")
#define CP_COMMIT() asm volatile("cp.async.commit_group;" ::: "memory")
#define CP_WAIT(n)  asm volatile("cp.async.wait_group %0;" :: "n"(n) : "memory")

#define LDSM_X4(r0, r1, r2, r3, addr)                                        \
    asm volatile("ldmatrix.sync.aligned.m8n8.x4.shared.b16 {%0,%1,%2,%3}, [%4];" \
                 : "=r"(r0), "=r"(r1), "=r"(r2), "=r"(r3) : "r"(addr))

#define MMA16816(d, a0, a1, a2, a3, b0, b1)                                  \
    asm volatile("mma.sync.aligned.m16n8k16.row.col.f32.bf16.bf16.f32 "      \
        "{%0,%1,%2,%3}, {%4,%5,%6,%7}, {%8,%9}, {%0,%1,%2,%3};"              \
        : "+f"((d)[0]), "+f"((d)[1]), "+f"((d)[2]), "+f"((d)[3])             \
        : "r"(a0), "r"(a1), "r"(a2), "r"(a3), "r"(b0), "r"(b1))

// ---------------- SMEM layout ----------------------------------------------
// A: 3 segs x (256 rows x 128B SW128) = 3 x 32KB
// B: 3 segs x (128 rows x 128B SW128) = 3 x 16KB
static constexpr int OFF_A  = 0;
static constexpr int OFF_B  = 98304;
static constexpr int OFF_XI = 147456;   // float4[256]
static constexpr int OFF_YI = 151552;   // float4[128]
static constexpr int SMEM_TOTAL = 153600;

// ---------------------------------------------------------------------------
// Pass 1: per-row precompute + bf16 split-expansion. One warp per row.
//   mx = x·mu (unscaled), row scaled by exp(0.5*logs2), h2 = 0.5*||x_||^2
//   bf16 split: x_ = hi + lo;  X: [hi|lo|hi], Y: [hi|hi|lo]
//   => X'·Y'^T = hi·hi + lo·hi + hi·lo  (missing lo·lo ~3e-5 abs)
// ---------------------------------------------------------------------------
__global__ void precomp_kernel(const float* __restrict__ src,
                               const float* __restrict__ mu,
                               const float* __restrict__ logs2, int isY)
{
    int gw = (blockIdx.x * blockDim.x + threadIdx.x) >> 5;  // global warp == row
    int l  = threadIdx.x & 31;

    float2 v   = ((const float2*)src)[gw * 32 + l];
    float2 muv = ((const float2*)mu)[l];
    float2 ls  = ((const float2*)logs2)[l];

    float s0 = expf(0.5f * ls.x), s1 = expf(0.5f * ls.y);
    float a = v.x * s0, c = v.y * s1;
    float m  = fmaf(v.x, muv.x, v.y * muv.y);
    float ss = fmaf(a, a, c * c);
#pragma unroll
    for (int o = 16; o > 0; o >>= 1) {
        m  += __shfl_xor_sync(0xffffffffu, m, o);
        ss += __shfl_xor_sync(0xffffffffu, ss, o);
    }

    __nv_bfloat16 h0 = __float2bfloat16(a);
    __nv_bfloat16 h1 = __float2bfloat16(c);
    __nv_bfloat16 l0 = __float2bfloat16(a - __bfloat162float(h0));
    __nv_bfloat16 l1 = __float2bfloat16(c - __bfloat162float(h1));
    uint32_t hi = ((uint32_t)__bfloat16_as_ushort(h1) << 16) | __bfloat16_as_ushort(h0);
    uint32_t lo = ((uint32_t)__bfloat16_as_ushort(l1) << 16) | __bfloat16_as_ushort(l0);

    uint32_t* dst = (uint32_t*)(isY ? g_Ye4 : g_Xe4) + (size_t)gw * (KE / 2);
    if (isY) {                 // [hi | hi | lo]
        dst[l] = hi; dst[32 + l] = hi; dst[64 + l] = lo;
    } else {                   // [hi | lo | hi]
        dst[l] = hi; dst[32 + l] = lo; dst[64 + l] = hi;
    }
    if (l == 0) {
        float sn, cs;
        sincosf(m, &sn, &cs);
        float4* ri = isY ? g_yr : g_xr;
        ri[gw] = make_float4(cs, sn, 0.5f * ss, 0.f);
    }
}

// ---------------------------------------------------------------------------
// Pass 2: pipelined mma.sync GEMM + fused epilogue.
//   CTA: 256x128 tile, 512 threads = 16 warps (4x4), warp tile 64x32.
//   K streamed as 3 cp.async commit groups (seg = 64 K-elems), compute seg s
//   after wait_group(2-s) -> loads of later segs overlap MMA of earlier ones.
// ---------------------------------------------------------------------------
__global__ void __launch_bounds__(512, 1)
pairwise_kernel(float* __restrict__ out)
{
    extern __shared__ char smem[];
    const uint32_t base = smem_u32(smem);
    const int tid = threadIdx.x;
    const int wid = tid >> 5;
    const int l   = tid & 31;
    const int wy  = wid >> 2;           // 0..3 : row block (64 rows)
    const int wx  = wid & 3;            // 0..3 : col block (32 cols)

    const int b  = blockIdx.z;
    const int n0 = blockIdx.y * 256;
    const int m0 = blockIdx.x * 128;

    const uint4* Ag = g_Xe4 + ((size_t)b * NN + n0) * (KE / 8);
    const uint4* Bg = g_Ye4 + ((size_t)b * MM + m0) * (KE / 8);

    // ---- issue 3 cp.async groups: seg s = K columns [s*64, s*64+64) ----
#pragma unroll
    for (int seg = 0; seg < 3; seg++) {
        const uint32_t dA = base + OFF_A + seg * 32768;
        const uint32_t dB = base + OFF_B + seg * 16384;
        // A-seg: 256 rows x 8 uint4 = 2048 -> 4 per thread
#pragma unroll
        for (int i = 0; i < 4; i++) {
            int f = i * 512 + tid;
            int row = f >> 3, c16 = f & 7;
            CP_ASYNC16(dA + SWZ((uint32_t)(row * 128 + c16 * 16)),
                       (const void*)(Ag + row * 24 + seg * 8 + c16));
        }
        // B-seg: 128 rows x 8 uint4 = 1024 -> 2 per thread
#pragma unroll
        for (int i = 0; i < 2; i++) {
            int f = i * 512 + tid;
            int row = f >> 3, c16 = f & 7;
            CP_ASYNC16(dB + SWZ((uint32_t)(row * 128 + c16 * 16)),
                       (const void*)(Bg + row * 24 + seg * 8 + c16));
        }
        CP_COMMIT();
    }

    // ---- row-info staging (plain LDG/STS, covered by first syncthreads) ----
    if (tid < 256)
        *(float4*)(smem + OFF_XI + tid * 16) = g_xr[(size_t)b * NN + n0 + tid];
    else if (tid < 384)
        *(float4*)(smem + OFF_YI + (tid - 256) * 16) = g_yr[(size_t)b * MM + m0 + (tid - 256)];

    // ---- per-lane ldmatrix address components ----
    const int arow  = wy * 64 + (l & 15);
    const uint32_t axor  = (uint32_t)((l & 7) * 16);
    const uint32_t ahalf = (uint32_t)((l >> 4) * 16);
    const int g     = l >> 3;
    const int brow  = wx * 32 + (g & 2) * 4 + (l & 7);
    const uint32_t bxor  = (uint32_t)((l & 7) * 16);
    const uint32_t bhalf = (uint32_t)((g & 1) * 16);

    float acc[4][4][4];
#pragma unroll
    for (int mt = 0; mt < 4; mt++)
#pragma unroll
        for (int nt = 0; nt < 4; nt++)
#pragma unroll
            for (int e = 0; e < 4; e++) acc[mt][nt][e] = 0.f;

    // ---- mainloop: 3 segs x 4 K16-steps ----
#pragma unroll
    for (int seg = 0; seg < 3; seg++) {
        if (seg == 0)      { CP_WAIT(2); }
        else if (seg == 1) { CP_WAIT(1); }
        else               { CP_WAIT(0); }
        __syncthreads();

        const uint32_t baseA = base + OFF_A + seg * 32768;
        const uint32_t baseB = base + OFF_B + seg * 16384;
#pragma unroll
        for (int ks = 0; ks < 4; ks++) {
            const uint32_t kb = (uint32_t)(ks * 32);
            uint32_t af[4][4];
#pragma unroll
            for (int mt = 0; mt < 4; mt++) {
                uint32_t addr = baseA + (uint32_t)((arow + mt * 16) * 128) + ((kb + ahalf) ^ axor);
                LDSM_X4(af[mt][0], af[mt][1], af[mt][2], af[mt][3], addr);
            }
            uint32_t bf[4][2];
#pragma unroll
            for (int p = 0; p < 2; p++) {
                uint32_t addr = baseB + (uint32_t)((brow + p * 16) * 128) + ((kb + bhalf) ^ bxor);
                uint32_t r0, r1, r2, r3;
                LDSM_X4(r0, r1, r2, r3, addr);
                bf[p * 2 + 0][0] = r0; bf[p * 2 + 0][1] = r1;
                bf[p * 2 + 1][0] = r2; bf[p * 2 + 1][1] = r3;
            }
#pragma unroll
            for (int mt = 0; mt < 4; mt++)
#pragma unroll
                for (int nt = 0; nt < 4; nt++)
                    MMA16816(acc[mt][nt], af[mt][0], af[mt][1], af[mt][2], af[mt][3],
                             bf[nt][0], bf[nt][1]);
        }
    }

    // ---- epilogue straight from registers ----
    const float LOG2E = 1.44269504f;
    const int lr = l >> 2;
    const int lc = (l & 3) * 2;
#pragma unroll
    for (int mt = 0; mt < 4; mt++) {
        const int r0 = wy * 64 + mt * 16 + lr;
        const float4 xi0 = *(const float4*)(smem + OFF_XI + r0 * 16);
        const float4 xi1 = *(const float4*)(smem + OFF_XI + (r0 + 8) * 16);
        float* orow0 = out + ((size_t)b * NN + n0 + r0) * MM + m0;
        float* orow1 = orow0 + (size_t)8 * MM;
#pragma unroll
        for (int nt = 0; nt < 4; nt++) {
            const int c = wx * 32 + nt * 8 + lc;
            const float4 y0 = *(const float4*)(smem + OFF_YI + c * 16);
            const float4 y1 = *(const float4*)(smem + OFF_YI + (c + 1) * 16);

            float e00, e01, e10, e11;
            asm("ex2.approx.f32 %0, %1;" : "=f"(e00)
                : "f"(fminf(acc[mt][nt][0] - xi0.z - y0.z, 0.f) * LOG2E));
            asm("ex2.approx.f32 %0, %1;" : "=f"(e01)
                : "f"(fminf(acc[mt][nt][1] - xi0.z - y1.z, 0.f) * LOG2E));
            asm("ex2.approx.f32 %0, %1;" : "=f"(e10)
                : "f"(fminf(acc[mt][nt][2] - xi1.z - y0.z, 0.f) * LOG2E));
            asm("ex2.approx.f32 %0, %1;" : "=f"(e11)
                : "f"(fminf(acc[mt][nt][3] - xi1.z - y1.z, 0.f) * LOG2E));

            float c00 = fmaf(xi0.x, y0.x, xi0.y * y0.y);
            float c01 = fmaf(xi0.x, y1.x, xi0.y * y1.y);
            float c10 = fmaf(xi1.x, y0.x, xi1.y * y0.y);
            float c11 = fmaf(xi1.x, y1.x, xi1.y * y1.y);

            *(float2*)(orow0 + c) = make_float2(c00 * e00, c01 * e01);
            *(float2*)(orow1 + c) = make_float2(c10 * e10, c11 * e11);
        }
    }
}

// ---------------------------------------------------------------------------
extern "C" void kernel_launch(void* const* d_in, const int* in_sizes, int n_in,
                              void* d_out, int out_size)
{
    const float* x     = (const float*)d_in[0];
    const float* y     = (const float*)d_in[1];
    const float* mu    = (const float*)d_in[2];
    const float* logs2 = (const float*)d_in[3];
    (void)in_sizes; (void)n_in; (void)out_size;

    cudaFuncSetAttribute(pairwise_kernel,
                         cudaFuncAttributeMaxDynamicSharedMemorySize, SMEM_TOTAL);

    precomp_kernel<<<(BB * NN) / 8, 256>>>(x, mu, logs2, 0);
    precomp_kernel<<<(BB * MM) / 8, 256>>>(y, mu, logs2, 1);

    dim3 grid(MM / 128, NN / 256, BB);
    pairwise_kernel<<<grid, 512, SMEM_TOTAL>>>((float*)d_out);
}

// round 11
// speedup vs baseline: 2.6727x; 1.1634x over previous
#include <cuda_runtime.h>
#include <cuda_bf16.h>
#include <math.h>
#include <stdint.h>

// Shape fixed by dataset: x[4,4096,64], y[4,4096,64], mu[64,1], logs2diag[64]
// Bisection note: R9/R10 (fused precomp + occ-2 pairwise) hit "container
// failed twice" twice in a row. This round reverts to the R8-proven two-launch
// precomp structure and keeps ONLY the occ-2 pairwise change under test.
#define BB 4
#define NN 4096
#define MM 4096
#define DD 64
#define KE 192                      // expanded K: [hi|lo|hi] / [hi|hi|lo]

// ---------------- device scratch (no allocation allowed) -------------------
__device__ uint4  g_Xe4[BB * NN * (KE / 8)];   // bf16 expanded X rows, 24 uint4/row
__device__ uint4  g_Ye4[BB * MM * (KE / 8)];   // bf16 expanded Y rows
__device__ float4 g_xr[BB * NN];               // {cos(mx), sin(mx), 0.5*||x_||^2*log2e, 0}
__device__ float4 g_yr[BB * MM];

__device__ __forceinline__ uint32_t smem_u32(const void* p) {
    uint32_t a;
    asm("{ .reg .u64 t; cvta.to.shared.u64 t, %1; cvt.u32.u64 %0, t; }" : "=r"(a) : "l"(p));
    return a;
}

#define SWZ(o) ((o) ^ (((o) >> 3) & 0x70))

#define CP_ASYNC16(dst, src) \
    asm volatile("cp.async.cg.shared.global [%0], [%1], 16;" \
                 :: "r"(dst), "l"(src) : "memory")
#define CP_COMMIT() asm volatile("cp.async.commit_group;" ::: "memory")
#define CP_WAIT(n)  asm volatile("cp.async.wait_group %0;" :: "n"(n) : "memory")

#define LDSM_X4(r0, r1, r2, r3, addr)                                        \
    asm volatile("ldmatrix.sync.aligned.m8n8.x4.shared.b16 {%0,%1,%2,%3}, [%4];" \
                 : "=r"(r0), "=r"(r1), "=r"(r2), "=r"(r3) : "r"(addr))

#define MMA16816(d, a0, a1, a2, a3, b0, b1)                                  \
    asm volatile("mma.sync.aligned.m16n8k16.row.col.f32.bf16.bf16.f32 "      \
        "{%0,%1,%2,%3}, {%4,%5,%6,%7}, {%8,%9}, {%0,%1,%2,%3};"              \
        : "+f"((d)[0]), "+f"((d)[1]), "+f"((d)[2]), "+f"((d)[3])             \
        : "r"(a0), "r"(a1), "r"(a2), "r"(a3), "r"(b0), "r"(b1))

// ---------------- SMEM layout (100KB -> 2 CTAs/SM) --------------------------
// A: 3 segs x (128 rows x 128B SW128) = 3 x 16KB ; B likewise.
static constexpr int OFF_A  = 0;
static constexpr int OFF_B  = 49152;
static constexpr int OFF_XI = 98304;    // float4[128]
static constexpr int OFF_YI = 100352;   // float4[128]
static constexpr int SMEM_TOTAL = 102400;

// ---------------------------------------------------------------------------
// Pass 1: per-row precompute + bf16 split-expansion. One warp per row.
//   (Structure identical to the R8-passing version; z-term now pre-multiplied
//   by log2(e) for the epilogue.)
//   mx = x·mu (unscaled), row scaled by exp(0.5*logs2), h2 = 0.5*||x_||^2
//   bf16 split: x_ = hi + lo;  X: [hi|lo|hi], Y: [hi|hi|lo]
//   => X'·Y'^T = hi·hi + lo·hi + hi·lo  (missing lo·lo ~3e-5 abs)
// ---------------------------------------------------------------------------
__global__ void precomp_kernel(const float* __restrict__ src,
                               const float* __restrict__ mu,
                               const float* __restrict__ logs2, int isY)
{
    int gw = (blockIdx.x * blockDim.x + threadIdx.x) >> 5;  // global warp == row
    int l  = threadIdx.x & 31;

    float2 v   = ((const float2*)src)[gw * 32 + l];
    float2 muv = ((const float2*)mu)[l];
    float2 ls  = ((const float2*)logs2)[l];

    float s0 = expf(0.5f * ls.x), s1 = expf(0.5f * ls.y);
    float a = v.x * s0, c = v.y * s1;
    float m  = fmaf(v.x, muv.x, v.y * muv.y);
    float ss = fmaf(a, a, c * c);
#pragma unroll
    for (int o = 16; o > 0; o >>= 1) {
        m  += __shfl_xor_sync(0xffffffffu, m, o);
        ss += __shfl_xor_sync(0xffffffffu, ss, o);
    }

    __nv_bfloat16 h0 = __float2bfloat16(a);
    __nv_bfloat16 h1 = __float2bfloat16(c);
    __nv_bfloat16 l0 = __float2bfloat16(a - __bfloat162float(h0));
    __nv_bfloat16 l1 = __float2bfloat16(c - __bfloat162float(h1));
    uint32_t hi = ((uint32_t)__bfloat16_as_ushort(h1) << 16) | __bfloat16_as_ushort(h0);
    uint32_t lo = ((uint32_t)__bfloat16_as_ushort(l1) << 16) | __bfloat16_as_ushort(l0);

    uint32_t* dst = (uint32_t*)(isY ? g_Ye4 : g_Xe4) + (size_t)gw * (KE / 2);
    if (isY) {                 // [hi | hi | lo]
        dst[l] = hi; dst[32 + l] = hi; dst[64 + l] = lo;
    } else {                   // [hi | lo | hi]
        dst[l] = hi; dst[32 + l] = lo; dst[64 + l] = hi;
    }
    if (l == 0) {
        float sn, cs;
        sincosf(m, &sn, &cs);
        float4* ri = isY ? g_yr : g_xr;
        ri[gw] = make_float4(cs, sn, 0.5f * ss * 1.44269504f, 0.f);
    }
}

// ---------------------------------------------------------------------------
// Pass 2: pipelined mma.sync GEMM + fused epilogue.
//   CTA: 128x128 tile, 256 threads = 8 warps (2x4), warp tile 64x32.
//   3 cp.async commit groups (seg = 64 K-elems); 100KB smem -> occ 2, so one
//   CTA's epilogue (MUFU/FMA/STG) overlaps the co-resident CTA's HMMA mainloop.
// ---------------------------------------------------------------------------
__global__ void __launch_bounds__(256, 2)
pairwise_kernel(float* __restrict__ out)
{
    extern __shared__ char smem[];
    const uint32_t base = smem_u32(smem);
    const int tid = threadIdx.x;
    const int wid = tid >> 5;
    const int l   = tid & 31;
    const int wy  = wid >> 2;           // 0..1 : row block (64 rows)
    const int wx  = wid & 3;            // 0..3 : col block (32 cols)

    const int b  = blockIdx.z;
    const int n0 = blockIdx.y * 128;
    const int m0 = blockIdx.x * 128;

    const uint4* Ag = g_Xe4 + ((size_t)b * NN + n0) * (KE / 8);
    const uint4* Bg = g_Ye4 + ((size_t)b * MM + m0) * (KE / 8);

    // ---- issue 3 cp.async groups: seg s = K columns [s*64, s*64+64) ----
#pragma unroll
    for (int seg = 0; seg < 3; seg++) {
        const uint32_t dA = base + OFF_A + seg * 16384;
        const uint32_t dB = base + OFF_B + seg * 16384;
        // each operand seg: 128 rows x 8 uint4 = 1024 -> 4 per thread
#pragma unroll
        for (int i = 0; i < 4; i++) {
            int f = i * 256 + tid;
            int row = f >> 3, c16 = f & 7;
            CP_ASYNC16(dA + SWZ((uint32_t)(row * 128 + c16 * 16)),
                       (const void*)(Ag + row * 24 + seg * 8 + c16));
            CP_ASYNC16(dB + SWZ((uint32_t)(row * 128 + c16 * 16)),
                       (const void*)(Bg + row * 24 + seg * 8 + c16));
        }
        CP_COMMIT();
    }

    // ---- row-info staging (plain LDG/STS, covered by first syncthreads) ----
    if (tid < 128)
        *(float4*)(smem + OFF_XI + tid * 16) = g_xr[(size_t)b * NN + n0 + tid];
    else
        *(float4*)(smem + OFF_YI + (tid - 128) * 16) = g_yr[(size_t)b * MM + m0 + (tid - 128)];

    // ---- per-lane ldmatrix address components ----
    const int arow  = wy * 64 + (l & 15);
    const uint32_t axor  = (uint32_t)((l & 7) * 16);
    const uint32_t ahalf = (uint32_t)((l >> 4) * 16);
    const int g     = l >> 3;
    const int brow  = wx * 32 + (g & 2) * 4 + (l & 7);
    const uint32_t bxor  = (uint32_t)((l & 7) * 16);
    const uint32_t bhalf = (uint32_t)((g & 1) * 16);

    float acc[4][4][4];
#pragma unroll
    for (int mt = 0; mt < 4; mt++)
#pragma unroll
        for (int nt = 0; nt < 4; nt++)
#pragma unroll
            for (int e = 0; e < 4; e++) acc[mt][nt][e] = 0.f;

    // ---- mainloop: 3 segs x 4 K16-steps ----
#pragma unroll
    for (int seg = 0; seg < 3; seg++) {
        if (seg == 0)      { CP_WAIT(2); }
        else if (seg == 1) { CP_WAIT(1); }
        else               { CP_WAIT(0); }
        __syncthreads();

        const uint32_t baseA = base + OFF_A + seg * 16384;
        const uint32_t baseB = base + OFF_B + seg * 16384;
#pragma unroll
        for (int ks = 0; ks < 4; ks++) {
            const uint32_t kb = (uint32_t)(ks * 32);
            uint32_t af[4][4];
#pragma unroll
            for (int mt = 0; mt < 4; mt++) {
                uint32_t addr = baseA + (uint32_t)((arow + mt * 16) * 128) + ((kb + ahalf) ^ axor);
                LDSM_X4(af[mt][0], af[mt][1], af[mt][2], af[mt][3], addr);
            }
            uint32_t bf[4][2];
#pragma unroll
            for (int p = 0; p < 2; p++) {
                uint32_t addr = baseB + (uint32_t)((brow + p * 16) * 128) + ((kb + bhalf) ^ bxor);
                uint32_t r0, r1, r2, r3;
                LDSM_X4(r0, r1, r2, r3, addr);
                bf[p * 2 + 0][0] = r0; bf[p * 2 + 0][1] = r1;
                bf[p * 2 + 1][0] = r2; bf[p * 2 + 1][1] = r3;
            }
#pragma unroll
            for (int mt = 0; mt < 4; mt++)
#pragma unroll
                for (int nt = 0; nt < 4; nt++)
                    MMA16816(acc[mt][nt], af[mt][0], af[mt][1], af[mt][2], af[mt][3],
                             bf[nt][0], bf[nt][1]);
        }
    }

    // ---- epilogue straight from registers ----
    // z-terms are pre-scaled by log2(e):  e = ex2(min(acc*L - (xz+yz), 0))
    const float LOG2E = 1.44269504f;
    const int lr = l >> 2;
    const int lc = (l & 3) * 2;
#pragma unroll
    for (int mt = 0; mt < 4; mt++) {
        const int r0 = wy * 64 + mt * 16 + lr;
        const float4 xi0 = *(const float4*)(smem + OFF_XI + r0 * 16);
        const float4 xi1 = *(const float4*)(smem + OFF_XI + (r0 + 8) * 16);
        float* orow0 = out + ((size_t)b * NN + n0 + r0) * MM + m0;
        float* orow1 = orow0 + (size_t)8 * MM;
#pragma unroll
        for (int nt = 0; nt < 4; nt++) {
            const int c = wx * 32 + nt * 8 + lc;
            const float4 y0 = *(const float4*)(smem + OFF_YI + c * 16);
            const float4 y1 = *(const float4*)(smem + OFF_YI + (c + 1) * 16);

            float z00 = xi0.z + y0.z, z01 = xi0.z + y1.z;
            float z10 = xi1.z + y0.z, z11 = xi1.z + y1.z;

            float e00, e01, e10, e11;
            asm("ex2.approx.f32 %0, %1;" : "=f"(e00)
                : "f"(fminf(fmaf(acc[mt][nt][0], LOG2E, -z00), 0.f)));
            asm("ex2.approx.f32 %0, %1;" : "=f"(e01)
                : "f"(fminf(fmaf(acc[mt][nt][1], LOG2E, -z01), 0.f)));
            asm("ex2.approx.f32 %0, %1;" : "=f"(e10)
                : "f"(fminf(fmaf(acc[mt][nt][2], LOG2E, -z10), 0.f)));
            asm("ex2.approx.f32 %0, %1;" : "=f"(e11)
                : "f"(fminf(fmaf(acc[mt][nt][3], LOG2E, -z11), 0.f)));

            float c00 = fmaf(xi0.x, y0.x, xi0.y * y0.y);
            float c01 = fmaf(xi0.x, y1.x, xi0.y * y1.y);
            float c10 = fmaf(xi1.x, y0.x, xi1.y * y0.y);
            float c11 = fmaf(xi1.x, y1.x, xi1.y * y1.y);

            *(float2*)(orow0 + c) = make_float2(c00 * e00, c01 * e01);
            *(float2*)(orow1 + c) = make_float2(c10 * e10, c11 * e11);
        }
    }
}

// ---------------------------------------------------------------------------
extern "C" void kernel_launch(void* const* d_in, const int* in_sizes, int n_in,
                              void* d_out, int out_size)
{
    const float* x     = (const float*)d_in[0];
    const float* y     = (const float*)d_in[1];
    const float* mu    = (const float*)d_in[2];
    const float* logs2 = (const float*)d_in[3];
    (void)in_sizes; (void)n_in; (void)out_size;

    cudaFuncSetAttribute(pairwise_kernel,
                         cudaFuncAttributeMaxDynamicSharedMemorySize, SMEM_TOTAL);

    // two launches, one warp per row (R8-proven structure)
    precomp_kernel<<<(BB * NN) / 8, 256>>>(x, mu, logs2, 0);
    precomp_kernel<<<(BB * MM) / 8, 256>>>(y, mu, logs2, 1);

    dim3 grid(MM / 128, NN / 128, BB);
    pairwise_kernel<<<grid, 256, SMEM_TOTAL>>>((float*)d_out);
}

// round 12
// speedup vs baseline: 2.7050x; 1.0121x over previous
#include <cuda_runtime.h>
#include <cuda_bf16.h>
#include <math.h>
#include <stdint.h>

// Shape fixed by dataset: x[4,4096,64], y[4,4096,64], mu[64,1], logs2diag[64]
// R12: pairwise kernel byte-identical to the 112.6us R11 version (occ-2
// overlap proven). Only change: the two precomp launches are fused into one
// via gridDim.y=2 (blockIdx.y selects X vs Y; per-thread code unchanged).
#define BB 4
#define NN 4096
#define MM 4096
#define DD 64
#define KE 192                      // expanded K: [hi|lo|hi] / [hi|hi|lo]

// ---------------- device scratch (no allocation allowed) -------------------
__device__ uint4  g_Xe4[BB * NN * (KE / 8)];   // bf16 expanded X rows, 24 uint4/row
__device__ uint4  g_Ye4[BB * MM * (KE / 8)];   // bf16 expanded Y rows
__device__ float4 g_xr[BB * NN];               // {cos(mx), sin(mx), 0.5*||x_||^2*log2e, 0}
__device__ float4 g_yr[BB * MM];

__device__ __forceinline__ uint32_t smem_u32(const void* p) {
    uint32_t a;
    asm("{ .reg .u64 t; cvta.to.shared.u64 t, %1; cvt.u32.u64 %0, t; }" : "=r"(a) : "l"(p));
    return a;
}

#define SWZ(o) ((o) ^ (((o) >> 3) & 0x70))

#define CP_ASYNC16(dst, src) \
    asm volatile("cp.async.cg.shared.global [%0], [%1], 16;" \
                 :: "r"(dst), "l"(src) : "memory")
#define CP_COMMIT() asm volatile("cp.async.commit_group;" ::: "memory")
#define CP_WAIT(n)  asm volatile("cp.async.wait_group %0;" :: "n"(n) : "memory")

#define LDSM_X4(r0, r1, r2, r3, addr)                                        \
    asm volatile("ldmatrix.sync.aligned.m8n8.x4.shared.b16 {%0,%1,%2,%3}, [%4];" \
                 : "=r"(r0), "=r"(r1), "=r"(r2), "=r"(r3) : "r"(addr))

#define MMA16816(d, a0, a1, a2, a3, b0, b1)                                  \
    asm volatile("mma.sync.aligned.m16n8k16.row.col.f32.bf16.bf16.f32 "      \
        "{%0,%1,%2,%3}, {%4,%5,%6,%7}, {%8,%9}, {%0,%1,%2,%3};"              \
        : "+f"((d)[0]), "+f"((d)[1]), "+f"((d)[2]), "+f"((d)[3])             \
        : "r"(a0), "r"(a1), "r"(a2), "r"(a3), "r"(b0), "r"(b1))

// ---------------- SMEM layout (100KB -> 2 CTAs/SM) --------------------------
// A: 3 segs x (128 rows x 128B SW128) = 3 x 16KB ; B likewise.
static constexpr int OFF_A  = 0;
static constexpr int OFF_B  = 49152;
static constexpr int OFF_XI = 98304;    // float4[128]
static constexpr int OFF_YI = 100352;   // float4[128]
static constexpr int SMEM_TOTAL = 102400;

// ---------------------------------------------------------------------------
// Pass 1 (single launch, gridDim.y=2): per-row precompute + bf16 split.
//   blockIdx.y == 0 -> X rows ([hi|lo|hi]);  == 1 -> Y rows ([hi|hi|lo])
//   Per-thread math identical to the R11-passing version.
// ---------------------------------------------------------------------------
__global__ void precomp_kernel(const float* __restrict__ x,
                               const float* __restrict__ y,
                               const float* __restrict__ mu,
                               const float* __restrict__ logs2)
{
    int gw  = (blockIdx.x * blockDim.x + threadIdx.x) >> 5;  // row within side
    int l   = threadIdx.x & 31;
    int isY = blockIdx.y;
    const float* src = isY ? y : x;

    float2 v   = ((const float2*)src)[gw * 32 + l];
    float2 muv = ((const float2*)mu)[l];
    float2 ls  = ((const float2*)logs2)[l];

    float s0 = expf(0.5f * ls.x), s1 = expf(0.5f * ls.y);
    float a = v.x * s0, c = v.y * s1;
    float m  = fmaf(v.x, muv.x, v.y * muv.y);
    float ss = fmaf(a, a, c * c);
#pragma unroll
    for (int o = 16; o > 0; o >>= 1) {
        m  += __shfl_xor_sync(0xffffffffu, m, o);
        ss += __shfl_xor_sync(0xffffffffu, ss, o);
    }

    __nv_bfloat16 h0 = __float2bfloat16(a);
    __nv_bfloat16 h1 = __float2bfloat16(c);
    __nv_bfloat16 l0 = __float2bfloat16(a - __bfloat162float(h0));
    __nv_bfloat16 l1 = __float2bfloat16(c - __bfloat162float(h1));
    uint32_t hi = ((uint32_t)__bfloat16_as_ushort(h1) << 16) | __bfloat16_as_ushort(h0);
    uint32_t lo = ((uint32_t)__bfloat16_as_ushort(l1) << 16) | __bfloat16_as_ushort(l0);

    uint32_t* dst = (uint32_t*)(isY ? g_Ye4 : g_Xe4) + (size_t)gw * (KE / 2);
    if (isY) {                 // [hi | hi | lo]
        dst[l] = hi; dst[32 + l] = hi; dst[64 + l] = lo;
    } else {                   // [hi | lo | hi]
        dst[l] = hi; dst[32 + l] = lo; dst[64 + l] = hi;
    }
    if (l == 0) {
        float sn, cs;
        sincosf(m, &sn, &cs);
        float4* ri = isY ? g_yr : g_xr;
        ri[gw] = make_float4(cs, sn, 0.5f * ss * 1.44269504f, 0.f);
    }
}

// ---------------------------------------------------------------------------
// Pass 2: pipelined mma.sync GEMM + fused epilogue. (byte-identical to R11)
//   CTA: 128x128 tile, 256 threads = 8 warps (2x4), warp tile 64x32.
//   3 cp.async commit groups (seg = 64 K-elems); 100KB smem -> occ 2, so one
//   CTA's epilogue (MUFU/FMA/STG) overlaps the co-resident CTA's HMMA mainloop.
// ---------------------------------------------------------------------------
__global__ void __launch_bounds__(256, 2)
pairwise_kernel(float* __restrict__ out)
{
    extern __shared__ char smem[];
    const uint32_t base = smem_u32(smem);
    const int tid = threadIdx.x;
    const int wid = tid >> 5;
    const int l   = tid & 31;
    const int wy  = wid >> 2;           // 0..1 : row block (64 rows)
    const int wx  = wid & 3;            // 0..3 : col block (32 cols)

    const int b  = blockIdx.z;
    const int n0 = blockIdx.y * 128;
    const int m0 = blockIdx.x * 128;

    const uint4* Ag = g_Xe4 + ((size_t)b * NN + n0) * (KE / 8);
    const uint4* Bg = g_Ye4 + ((size_t)b * MM + m0) * (KE / 8);

    // ---- issue 3 cp.async groups: seg s = K columns [s*64, s*64+64) ----
#pragma unroll
    for (int seg = 0; seg < 3; seg++) {
        const uint32_t dA = base + OFF_A + seg * 16384;
        const uint32_t dB = base + OFF_B + seg * 16384;
        // each operand seg: 128 rows x 8 uint4 = 1024 -> 4 per thread
#pragma unroll
        for (int i = 0; i < 4; i++) {
            int f = i * 256 + tid;
            int row = f >> 3, c16 = f & 7;
            CP_ASYNC16(dA + SWZ((uint32_t)(row * 128 + c16 * 16)),
                       (const void*)(Ag + row * 24 + seg * 8 + c16));
            CP_ASYNC16(dB + SWZ((uint32_t)(row * 128 + c16 * 16)),
                       (const void*)(Bg + row * 24 + seg * 8 + c16));
        }
        CP_COMMIT();
    }

    // ---- row-info staging (plain LDG/STS, covered by first syncthreads) ----
    if (tid < 128)
        *(float4*)(smem + OFF_XI + tid * 16) = g_xr[(size_t)b * NN + n0 + tid];
    else
        *(float4*)(smem + OFF_YI + (tid - 128) * 16) = g_yr[(size_t)b * MM + m0 + (tid - 128)];

    // ---- per-lane ldmatrix address components ----
    const int arow  = wy * 64 + (l & 15);
    const uint32_t axor  = (uint32_t)((l & 7) * 16);
    const uint32_t ahalf = (uint32_t)((l >> 4) * 16);
    const int g     = l >> 3;
    const int brow  = wx * 32 + (g & 2) * 4 + (l & 7);
    const uint32_t bxor  = (uint32_t)((l & 7) * 16);
    const uint32_t bhalf = (uint32_t)((g & 1) * 16);

    float acc[4][4][4];
#pragma unroll
    for (int mt = 0; mt < 4; mt++)
#pragma unroll
        for (int nt = 0; nt < 4; nt++)
#pragma unroll
            for (int e = 0; e < 4; e++) acc[mt][nt][e] = 0.f;

    // ---- mainloop: 3 segs x 4 K16-steps ----
#pragma unroll
    for (int seg = 0; seg < 3; seg++) {
        if (seg == 0)      { CP_WAIT(2); }
        else if (seg == 1) { CP_WAIT(1); }
        else               { CP_WAIT(0); }
        __syncthreads();

        const uint32_t baseA = base + OFF_A + seg * 16384;
        const uint32_t baseB = base + OFF_B + seg * 16384;
#pragma unroll
        for (int ks = 0; ks < 4; ks++) {
            const uint32_t kb = (uint32_t)(ks * 32);
            uint32_t af[4][4];
#pragma unroll
            for (int mt = 0; mt < 4; mt++) {
                uint32_t addr = baseA + (uint32_t)((arow + mt * 16) * 128) + ((kb + ahalf) ^ axor);
                LDSM_X4(af[mt][0], af[mt][1], af[mt][2], af[mt][3], addr);
            }
            uint32_t bf[4][2];
#pragma unroll
            for (int p = 0; p < 2; p++) {
                uint32_t addr = baseB + (uint32_t)((brow + p * 16) * 128) + ((kb + bhalf) ^ bxor);
                uint32_t r0, r1, r2, r3;
                LDSM_X4(r0, r1, r2, r3, addr);
                bf[p * 2 + 0][0] = r0; bf[p * 2 + 0][1] = r1;
                bf[p * 2 + 1][0] = r2; bf[p * 2 + 1][1] = r3;
            }
#pragma unroll
            for (int mt = 0; mt < 4; mt++)
#pragma unroll
                for (int nt = 0; nt < 4; nt++)
                    MMA16816(acc[mt][nt], af[mt][0], af[mt][1], af[mt][2], af[mt][3],
                             bf[nt][0], bf[nt][1]);
        }
    }

    // ---- epilogue straight from registers ----
    // z-terms are pre-scaled by log2(e):  e = ex2(min(acc*L - (xz+yz), 0))
    const float LOG2E = 1.44269504f;
    const int lr = l >> 2;
    const int lc = (l & 3) * 2;
#pragma unroll
    for (int mt = 0; mt < 4; mt++) {
        const int r0 = wy * 64 + mt * 16 + lr;
        const float4 xi0 = *(const float4*)(smem + OFF_XI + r0 * 16);
        const float4 xi1 = *(const float4*)(smem + OFF_XI + (r0 + 8) * 16);
        float* orow0 = out + ((size_t)b * NN + n0 + r0) * MM + m0;
        float* orow1 = orow0 + (size_t)8 * MM;
#pragma unroll
        for (int nt = 0; nt < 4; nt++) {
            const int c = wx * 32 + nt * 8 + lc;
            const float4 y0 = *(const float4*)(smem + OFF_YI + c * 16);
            const float4 y1 = *(const float4*)(smem + OFF_YI + (c + 1) * 16);

            float z00 = xi0.z + y0.z, z01 = xi0.z + y1.z;
            float z10 = xi1.z + y0.z, z11 = xi1.z + y1.z;

            float e00, e01, e10, e11;
            asm("ex2.approx.f32 %0, %1;" : "=f"(e00)
                : "f"(fminf(fmaf(acc[mt][nt][0], LOG2E, -z00), 0.f)));
            asm("ex2.approx.f32 %0, %1;" : "=f"(e01)
                : "f"(fminf(fmaf(acc[mt][nt][1], LOG2E, -z01), 0.f)));
            asm("ex2.approx.f32 %0, %1;" : "=f"(e10)
                : "f"(fminf(fmaf(acc[mt][nt][2], LOG2E, -z10), 0.f)));
            asm("ex2.approx.f32 %0, %1;" : "=f"(e11)
                : "f"(fminf(fmaf(acc[mt][nt][3], LOG2E, -z11), 0.f)));

            float c00 = fmaf(xi0.x, y0.x, xi0.y * y0.y);
            float c01 = fmaf(xi0.x, y1.x, xi0.y * y1.y);
            float c10 = fmaf(xi1.x, y0.x, xi1.y * y0.y);
            float c11 = fmaf(xi1.x, y1.x, xi1.y * y1.y);

            *(float2*)(orow0 + c) = make_float2(c00 * e00, c01 * e01);
            *(float2*)(orow1 + c) = make_float2(c10 * e10, c11 * e11);
        }
    }
}

// ---------------------------------------------------------------------------
extern "C" void kernel_launch(void* const* d_in, const int* in_sizes, int n_in,
                              void* d_out, int out_size)
{
    const float* x     = (const float*)d_in[0];
    const float* y     = (const float*)d_in[1];
    const float* mu    = (const float*)d_in[2];
    const float* logs2 = (const float*)d_in[3];
    (void)in_sizes; (void)n_in; (void)out_size;

    cudaFuncSetAttribute(pairwise_kernel,
                         cudaFuncAttributeMaxDynamicSharedMemorySize, SMEM_TOTAL);

    // single fused precomp launch: gridDim = (2048, 2), blockIdx.y selects X/Y
    dim3 pgrid((BB * NN) / 8, 2, 1);
    precomp_kernel<<<pgrid, 256>>>(x, y, mu, logs2);

    dim3 grid(MM / 128, NN / 128, BB);
    pairwise_kernel<<<grid, 256, SMEM_TOTAL>>>((float*)d_out);
}

// round 14
// speedup vs baseline: 3.0605x; 1.1314x over previous
#include <cuda_runtime.h>
#include <cuda_bf16.h>
#include <math.h>
#include <stdint.h>

// Shape fixed by dataset: x[4,4096,64], y[4,4096,64], mu[64,1], logs2diag[64]
// R14: VERBATIM resubmission of R13 (dedup split-bf16). R13 returned the
// broker-side "GB300 container failed twice" signature (seen for the
// untouched stub in R0; R7's identical resubmission passed in R8). Audit
// re-verified cp.async group/LDSM swizzle correspondence, reg budget (~115
// < 128 cap), smem 68KB. Measuring the dedup hypothesis: -33% L1 traffic
// in an L1-bound (79.6%) kernel.
#define BB 4
#define NN 4096
#define MM 4096
#define DD 64

// ---------------- device scratch (no allocation allowed) -------------------
// Row layout: 16 uint4 = [hi: 8 uint4 (K=64 bf16)][lo: 8 uint4]
__device__ uint4  g_XE[BB * NN * 16];
__device__ uint4  g_YE[BB * MM * 16];
__device__ float4 g_xr[BB * NN];   // {cos(mx), sin(mx), 0.5*||x_||^2*log2e, 0}
__device__ float4 g_yr[BB * MM];

__device__ __forceinline__ uint32_t smem_u32(const void* p) {
    uint32_t a;
    asm("{ .reg .u64 t; cvta.to.shared.u64 t, %1; cvt.u32.u64 %0, t; }" : "=r"(a) : "l"(p));
    return a;
}

#define SWZ(o) ((o) ^ (((o) >> 3) & 0x70))

#define CP_ASYNC16(dst, src) \
    asm volatile("cp.async.cg.shared.global [%0], [%1], 16;" \
                 :: "r"(dst), "l"(src) : "memory")
#define CP_COMMIT() asm volatile("cp.async.commit_group;" ::: "memory")
#define CP_WAIT(n)  asm volatile("cp.async.wait_group %0;" :: "n"(n) : "memory")

#define LDSM_X4(r0, r1, r2, r3, addr)                                        \
    asm volatile("ldmatrix.sync.aligned.m8n8.x4.shared.b16 {%0,%1,%2,%3}, [%4];" \
                 : "=r"(r0), "=r"(r1), "=r"(r2), "=r"(r3) : "r"(addr))

#define MMA16816(d, a0, a1, a2, a3, b0, b1)                                  \
    asm volatile("mma.sync.aligned.m16n8k16.row.col.f32.bf16.bf16.f32 "      \
        "{%0,%1,%2,%3}, {%4,%5,%6,%7}, {%8,%9}, {%0,%1,%2,%3};"              \
        : "+f"((d)[0]), "+f"((d)[1]), "+f"((d)[2]), "+f"((d)[3])             \
        : "r"(a0), "r"(a1), "r"(a2), "r"(a3), "r"(b0), "r"(b1))

// ---------------- SMEM layout (~68KB -> 2 CTAs/SM) --------------------------
static constexpr int SEG_AH = 0;         // Ahi: 128 rows x 128B SW128
static constexpr int SEG_AL = 16384;     // Alo
static constexpr int SEG_BH = 32768;     // Bhi
static constexpr int SEG_BL = 49152;     // Blo
static constexpr int OFF_XI = 65536;     // float4[128]
static constexpr int OFF_YI = 67584;     // float4[128]
static constexpr int SMEM_TOTAL = 69632;

// ---------------------------------------------------------------------------
// Pass 1 (single launch, gridDim.y=2): per-row precompute + bf16 split.
//   Row layout out: [hi(8 uint4) | lo(8 uint4)] — NO duplicated segment.
// ---------------------------------------------------------------------------
__global__ void precomp_kernel(const float* __restrict__ x,
                               const float* __restrict__ y,
                               const float* __restrict__ mu,
                               const float* __restrict__ logs2)
{
    int gw  = (blockIdx.x * blockDim.x + threadIdx.x) >> 5;  // row within side
    int l   = threadIdx.x & 31;
    int isY = blockIdx.y;
    const float* src = isY ? y : x;

    float2 v   = ((const float2*)src)[gw * 32 + l];
    float2 muv = ((const float2*)mu)[l];
    float2 ls  = ((const float2*)logs2)[l];

    float s0 = expf(0.5f * ls.x), s1 = expf(0.5f * ls.y);
    float a = v.x * s0, c = v.y * s1;
    float m  = fmaf(v.x, muv.x, v.y * muv.y);
    float ss = fmaf(a, a, c * c);
#pragma unroll
    for (int o = 16; o > 0; o >>= 1) {
        m  += __shfl_xor_sync(0xffffffffu, m, o);
        ss += __shfl_xor_sync(0xffffffffu, ss, o);
    }

    __nv_bfloat16 h0 = __float2bfloat16(a);
    __nv_bfloat16 h1 = __float2bfloat16(c);
    __nv_bfloat16 l0 = __float2bfloat16(a - __bfloat162float(h0));
    __nv_bfloat16 l1 = __float2bfloat16(c - __bfloat162float(h1));
    uint32_t hi = ((uint32_t)__bfloat16_as_ushort(h1) << 16) | __bfloat16_as_ushort(h0);
    uint32_t lo = ((uint32_t)__bfloat16_as_ushort(l1) << 16) | __bfloat16_as_ushort(l0);

    uint32_t* dst = (uint32_t*)(isY ? g_YE : g_XE) + (size_t)gw * 64;
    dst[l] = hi; dst[32 + l] = lo;

    if (l == 0) {
        float sn, cs;
        sincosf(m, &sn, &cs);
        float4* ri = isY ? g_yr : g_xr;
        ri[gw] = make_float4(cs, sn, 0.5f * ss * 1.44269504f, 0.f);
    }
}

// ---------------------------------------------------------------------------
// Pass 2: dedup split-bf16 mma.sync GEMM + fused epilogue.
//   CTA: 128x128 tile, 256 threads = 8 warps (2x4), warp tile 64x32.
//   Per K16-step: (Ahi,Bhi) + (Alo,Bhi) + (Ahi,Blo) with hi fragments reused
//   in registers. 2 cp.async commit groups (K halves) for load/compute overlap.
// ---------------------------------------------------------------------------
__global__ void __launch_bounds__(256, 2)
pairwise_kernel(float* __restrict__ out)
{
    extern __shared__ char smem[];
    const uint32_t base = smem_u32(smem);
    const int tid = threadIdx.x;
    const int wid = tid >> 5;
    const int l   = tid & 31;
    const int wy  = wid >> 2;           // 0..1 : row block (64 rows)
    const int wx  = wid & 3;            // 0..3 : col block (32 cols)

    const int b  = blockIdx.z;
    const int n0 = blockIdx.y * 128;
    const int m0 = blockIdx.x * 128;

    const uint4* Ag = g_XE + ((size_t)b * NN + n0) * 16;
    const uint4* Bg = g_YE + ((size_t)b * MM + m0) * 16;

    // ---- cp.async: 2 groups split by K-half (logical c16 0..3 then 4..7) ----
    // Each seg: 128 rows x 8 uint4; per half: 512 uint4 -> 2 per thread.
#pragma unroll
    for (int half = 0; half < 2; half++) {
#pragma unroll
        for (int i = 0; i < 2; i++) {
            int f   = i * 256 + tid;
            int row = f >> 2;
            int c16 = (f & 3) + half * 4;
            uint32_t soff = SWZ((uint32_t)(row * 128 + c16 * 16));
            CP_ASYNC16(base + SEG_AH + soff, (const void*)(Ag + row * 16 + c16));
            CP_ASYNC16(base + SEG_AL + soff, (const void*)(Ag + row * 16 + 8 + c16));
            CP_ASYNC16(base + SEG_BH + soff, (const void*)(Bg + row * 16 + c16));
            CP_ASYNC16(base + SEG_BL + soff, (const void*)(Bg + row * 16 + 8 + c16));
        }
        CP_COMMIT();
    }

    // ---- row-info staging (covered by first syncthreads) ----
    if (tid < 128)
        *(float4*)(smem + OFF_XI + tid * 16) = g_xr[(size_t)b * NN + n0 + tid];
    else
        *(float4*)(smem + OFF_YI + (tid - 128) * 16) = g_yr[(size_t)b * MM + m0 + (tid - 128)];

    // ---- per-lane ldmatrix address components ----
    const int arow  = wy * 64 + (l & 15);
    const uint32_t axor  = (uint32_t)((l & 7) * 16);
    const uint32_t ahalf = (uint32_t)((l >> 4) * 16);
    const int g     = l >> 3;
    const int brow  = wx * 32 + (g & 2) * 4 + (l & 7);
    const uint32_t bxor  = (uint32_t)((l & 7) * 16);
    const uint32_t bhalf = (uint32_t)((g & 1) * 16);

    float acc[4][4][4];
#pragma unroll
    for (int mt = 0; mt < 4; mt++)
#pragma unroll
        for (int nt = 0; nt < 4; nt++)
#pragma unroll
            for (int e = 0; e < 4; e++) acc[mt][nt][e] = 0.f;

    // ---- mainloop: 4 K16-steps, 3 products per step, hi fragments reused ----
#pragma unroll
    for (int ks = 0; ks < 4; ks++) {
        if (ks == 0)      { CP_WAIT(1); __syncthreads(); }
        else if (ks == 2) { CP_WAIT(0); __syncthreads(); }

        const uint32_t kb   = (uint32_t)(ks * 32);
        const uint32_t aoff = (uint32_t)(arow * 128) + ((kb + ahalf) ^ axor);
        const uint32_t boff = (uint32_t)(brow * 128) + ((kb + bhalf) ^ bxor);

        uint32_t bh[4][2];
#pragma unroll
        for (int p = 0; p < 2; p++) {
            uint32_t r0, r1, r2, r3;
            LDSM_X4(r0, r1, r2, r3, base + SEG_BH + boff + (uint32_t)(p * 2048));
            bh[p * 2 + 0][0] = r0; bh[p * 2 + 0][1] = r1;
            bh[p * 2 + 1][0] = r2; bh[p * 2 + 1][1] = r3;
        }
        uint32_t ah[4][4];
#pragma unroll
        for (int mt = 0; mt < 4; mt++)
            LDSM_X4(ah[mt][0], ah[mt][1], ah[mt][2], ah[mt][3],
                    base + SEG_AH + aoff + (uint32_t)(mt * 2048));
        // hi . hi
#pragma unroll
        for (int mt = 0; mt < 4; mt++)
#pragma unroll
            for (int nt = 0; nt < 4; nt++)
                MMA16816(acc[mt][nt], ah[mt][0], ah[mt][1], ah[mt][2], ah[mt][3],
                         bh[nt][0], bh[nt][1]);

        // lo . hi  (Bhi reused)
#pragma unroll
        for (int mt = 0; mt < 4; mt++) {
            uint32_t al0, al1, al2, al3;
            LDSM_X4(al0, al1, al2, al3, base + SEG_AL + aoff + (uint32_t)(mt * 2048));
#pragma unroll
            for (int nt = 0; nt < 4; nt++)
                MMA16816(acc[mt][nt], al0, al1, al2, al3, bh[nt][0], bh[nt][1]);
        }

        // hi . lo  (Ahi reused)
        uint32_t bl[4][2];
#pragma unroll
        for (int p = 0; p < 2; p++) {
            uint32_t r0, r1, r2, r3;
            LDSM_X4(r0, r1, r2, r3, base + SEG_BL + boff + (uint32_t)(p * 2048));
            bl[p * 2 + 0][0] = r0; bl[p * 2 + 0][1] = r1;
            bl[p * 2 + 1][0] = r2; bl[p * 2 + 1][1] = r3;
        }
#pragma unroll
        for (int mt = 0; mt < 4; mt++)
#pragma unroll
            for (int nt = 0; nt < 4; nt++)
                MMA16816(acc[mt][nt], ah[mt][0], ah[mt][1], ah[mt][2], ah[mt][3],
                         bl[nt][0], bl[nt][1]);
    }

    // ---- epilogue straight from registers; y-info hoisted out of mt loop ----
    const float LOG2E = 1.44269504f;
    const int lr = l >> 2;
    const int lc = (l & 3) * 2;

    float4 ya[4], yb[4];
#pragma unroll
    for (int nt = 0; nt < 4; nt++) {
        const int c = wx * 32 + nt * 8 + lc;
        ya[nt] = *(const float4*)(smem + OFF_YI + c * 16);
        yb[nt] = *(const float4*)(smem + OFF_YI + (c + 1) * 16);
    }

#pragma unroll
    for (int mt = 0; mt < 4; mt++) {
        const int r0 = wy * 64 + mt * 16 + lr;
        const float4 xi0 = *(const float4*)(smem + OFF_XI + r0 * 16);
        const float4 xi1 = *(const float4*)(smem + OFF_XI + (r0 + 8) * 16);
        float* orow0 = out + ((size_t)b * NN + n0 + r0) * MM + m0;
        float* orow1 = orow0 + (size_t)8 * MM;
#pragma unroll
        for (int nt = 0; nt < 4; nt++) {
            const int c = wx * 32 + nt * 8 + lc;
            const float4 y0 = ya[nt];
            const float4 y1 = yb[nt];

            float z00 = xi0.z + y0.z, z01 = xi0.z + y1.z;
            float z10 = xi1.z + y0.z, z11 = xi1.z + y1.z;

            float e00, e01, e10, e11;
            asm("ex2.approx.f32 %0, %1;" : "=f"(e00)
                : "f"(fminf(fmaf(acc[mt][nt][0], LOG2E, -z00), 0.f)));
            asm("ex2.approx.f32 %0, %1;" : "=f"(e01)
                : "f"(fminf(fmaf(acc[mt][nt][1], LOG2E, -z01), 0.f)));
            asm("ex2.approx.f32 %0, %1;" : "=f"(e10)
                : "f"(fminf(fmaf(acc[mt][nt][2], LOG2E, -z10), 0.f)));
            asm("ex2.approx.f32 %0, %1;" : "=f"(e11)
                : "f"(fminf(fmaf(acc[mt][nt][3], LOG2E, -z11), 0.f)));

            float c00 = fmaf(xi0.x, y0.x, xi0.y * y0.y);
            float c01 = fmaf(xi0.x, y1.x, xi0.y * y1.y);
            float c10 = fmaf(xi1.x, y0.x, xi1.y * y0.y);
            float c11 = fmaf(xi1.x, y1.x, xi1.y * y1.y);

            *(float2*)(orow0 + c) = make_float2(c00 * e00, c01 * e01);
            *(float2*)(orow1 + c) = make_float2(c10 * e10, c11 * e11);
        }
    }
}

// ---------------------------------------------------------------------------
extern "C" void kernel_launch(void* const* d_in, const int* in_sizes, int n_in,
                              void* d_out, int out_size)
{
    const float* x     = (const float*)d_in[0];
    const float* y     = (const float*)d_in[1];
    const float* mu    = (const float*)d_in[2];
    const float* logs2 = (const float*)d_in[3];
    (void)in_sizes; (void)n_in; (void)out_size;

    cudaFuncSetAttribute(pairwise_kernel,
                         cudaFuncAttributeMaxDynamicSharedMemorySize, SMEM_TOTAL);

    dim3 pgrid((BB * NN) / 8, 2, 1);
    precomp_kernel<<<pgrid, 256>>>(x, y, mu, logs2);

    dim3 grid(MM / 128, NN / 128, BB);
    pairwise_kernel<<<grid, 256, SMEM_TOTAL>>>((float*)d_out);
}